// round 2
// baseline (speedup 1.0000x reference)
#include <cuda_runtime.h>
#include <cuda_bf16.h>
#include <cstdint>

#define N_NODES 100000
#define N_EDGES 3200000
#define F 128
#define KDIM 256   // combined [agg | x]

// ---------------- scratch (static device globals; no allocation) -------------
__device__ int   g_is64;
__device__ int   g_src[N_EDGES];
__device__ int   g_dst[N_EDGES];
__device__ int   g_csr_src[N_EDGES];
__device__ int   g_deg[N_NODES];
__device__ int   g_off[N_NODES + 1];
__device__ int   g_cursor[N_NODES];
__device__ float g_deginv[N_NODES];
__device__ float g_agg[(size_t)N_NODES * F];
__device__ float g_h0[(size_t)N_NODES * F];
__device__ float g_h1[(size_t)N_NODES * F];

// ---------------- setup kernels ---------------------------------------------
__global__ void zero_deg_kernel() {
    int i = blockIdx.x * blockDim.x + threadIdx.x;
    if (i < N_NODES) g_deg[i] = 0;
    if (i == 0) g_is64 = 1;   // assume int64 until a nonzero odd word proves otherwise
}

// Detect dtype of edge_index. Both layouts guarantee at least 2*N_EDGES int32
// words. If the data is int64 (values < 2^31), every odd word is 0.
__global__ void detect_kernel(const int* __restrict__ w) {
    int i = blockIdx.x * blockDim.x + threadIdx.x;  // word-pair index
    if (i < N_EDGES) {
        if (w[2 * i + 1] != 0) g_is64 = 0;  // plain store: any writer writes 0
    }
}

__global__ void edge_prep_kernel(const int* __restrict__ w) {
    int e = blockIdx.x * blockDim.x + threadIdx.x;
    if (e < N_EDGES) {
        int s, d;
        if (g_is64) {
            s = w[2 * e];
            d = w[2 * (N_EDGES + e)];
        } else {
            s = w[e];
            d = w[N_EDGES + e];
        }
        s = min(max(s, 0), N_NODES - 1);
        d = min(max(d, 0), N_NODES - 1);
        g_src[e] = s;
        g_dst[e] = d;
        atomicAdd(&g_deg[d], 1);
    }
}

// single-block exclusive scan over g_deg -> g_off, g_cursor, g_deginv
__global__ void scan_kernel() {
    __shared__ int wsum[32];
    __shared__ int carry;
    int t = threadIdx.x, lane = t & 31, w = t >> 5;
    if (t == 0) carry = 0;
    __syncthreads();
    for (int base = 0; base < N_NODES; base += 1024) {
        int i = base + t;
        int v = (i < N_NODES) ? g_deg[i] : 0;
        int x = v;
        #pragma unroll
        for (int d = 1; d < 32; d <<= 1) {
            int y = __shfl_up_sync(0xffffffffu, x, d);
            if (lane >= d) x += y;
        }
        if (lane == 31) wsum[w] = x;
        __syncthreads();
        if (w == 0) {
            int y = wsum[lane];
            #pragma unroll
            for (int d = 1; d < 32; d <<= 1) {
                int z = __shfl_up_sync(0xffffffffu, y, d);
                if (lane >= d) y += z;
            }
            wsum[lane] = y;
        }
        __syncthreads();
        int excl = carry + (x - v) + (w > 0 ? wsum[w - 1] : 0);
        if (i < N_NODES) {
            g_off[i]    = excl;
            g_cursor[i] = excl;
            g_deginv[i] = 1.0f / fmaxf((float)v, 1.0f);
        }
        int total = wsum[31];
        __syncthreads();
        if (t == 0) carry += total;
        __syncthreads();
    }
    if (t == 0) g_off[N_NODES] = carry;
}

__global__ void csr_fill_kernel() {
    int e = blockIdx.x * blockDim.x + threadIdx.x;
    if (e < N_EDGES) {
        int d = g_dst[e];
        int p = atomicAdd(&g_cursor[d], 1);
        if (p >= 0 && p < N_EDGES) g_csr_src[p] = g_src[e];
    }
}

// ---------------- aggregation: warp per node, pull via CSR -------------------
__global__ void agg_kernel(const float* __restrict__ in, float* __restrict__ out) {
    int gw   = (blockIdx.x * blockDim.x + threadIdx.x) >> 5;
    int lane = threadIdx.x & 31;
    if (gw >= N_NODES) return;
    int off0 = g_off[gw];
    int off1 = g_off[gw + 1];
    float4 acc = make_float4(0.f, 0.f, 0.f, 0.f);
    for (int base = off0; base < off1; base += 32) {
        int idx = base + lane;
        int s = (idx < off1) ? g_csr_src[idx] : 0;
        int cnt = min(32, off1 - base);
        #pragma unroll 4
        for (int j = 0; j < cnt; ++j) {
            int sj = __shfl_sync(0xffffffffu, s, j);
            const float4 v = __ldg(reinterpret_cast<const float4*>(in) + (size_t)sj * 32 + lane);
            acc.x += v.x; acc.y += v.y; acc.z += v.z; acc.w += v.w;
        }
    }
    float dinv = g_deginv[gw];
    float4 r = make_float4(acc.x * dinv, acc.y * dinv, acc.z * dinv, acc.w * dinv);
    reinterpret_cast<float4*>(out)[(size_t)gw * 32 + lane] = r;
}

// ---------------- fused GEMM: out = relu([agg|x] @ [Wl|Wr]^T + b) ------------
// Tile: 64 nodes x 128 outputs, K=256. 256 threads, thread tile 4 nodes x 8 outs.
#define BN 64
#define AS_STRIDE 68    // 64 + 4 pad
#define WS_STRIDE 132   // 128 + 4 pad
#define GEMM_SMEM ((256 * AS_STRIDE + 256 * WS_STRIDE) * 4)

__global__ void gemm_kernel(const float* __restrict__ agg, const float* __restrict__ xin,
                            const float* __restrict__ wl,  const float* __restrict__ wr,
                            const float* __restrict__ bias, float* __restrict__ out) {
    extern __shared__ float smem[];
    float* As = smem;                    // [K=256][AS_STRIDE] k-major
    float* Ws = smem + 256 * AS_STRIDE;  // [K=256][WS_STRIDE] k-major

    int t  = threadIdx.x;
    int n0 = blockIdx.x * BN;

    // load A tile transposed: iteration i = node row, t = k
    {
        int k = t;  // 0..255
        const int node_limit = N_NODES - n0;
        #pragma unroll 4
        for (int i = 0; i < BN; ++i) {
            float v = 0.f;
            if (i < node_limit) {
                size_t row = (size_t)(n0 + i) * F;
                v = (k < F) ? agg[row + k] : xin[row + (k - F)];
            }
            As[k * AS_STRIDE + i] = v;
        }
    }
    // load W combined transposed: iteration j = output row, t = k
    {
        int k = t;
        #pragma unroll 4
        for (int j = 0; j < F; ++j) {
            float v = (k < F) ? wl[j * F + k] : wr[j * F + (k - F)];
            Ws[k * WS_STRIDE + j] = v;
        }
    }
    __syncthreads();

    int jg = t & 15;   // output group: outs jg*4..+3 and 64+jg*4..+3
    int ng = t >> 4;   // node group: nodes ng*4..+3

    float acc[4][8];
    #pragma unroll
    for (int i = 0; i < 4; ++i)
        #pragma unroll
        for (int j = 0; j < 8; ++j) acc[i][j] = 0.f;

    #pragma unroll 8
    for (int k = 0; k < KDIM; ++k) {
        float4 a  = *reinterpret_cast<const float4*>(&As[k * AS_STRIDE + ng * 4]);
        float4 b0 = *reinterpret_cast<const float4*>(&Ws[k * WS_STRIDE + jg * 4]);
        float4 b1 = *reinterpret_cast<const float4*>(&Ws[k * WS_STRIDE + 64 + jg * 4]);
        float av[4] = {a.x, a.y, a.z, a.w};
        float bv[8] = {b0.x, b0.y, b0.z, b0.w, b1.x, b1.y, b1.z, b1.w};
        #pragma unroll
        for (int i = 0; i < 4; ++i)
            #pragma unroll
            for (int j = 0; j < 8; ++j)
                acc[i][j] += av[i] * bv[j];
    }

    float4 bb0 = *reinterpret_cast<const float4*>(&bias[jg * 4]);
    float4 bb1 = *reinterpret_cast<const float4*>(&bias[64 + jg * 4]);

    #pragma unroll
    for (int i = 0; i < 4; ++i) {
        int node = n0 + ng * 4 + i;
        if (node < N_NODES) {
            float4 r0, r1;
            r0.x = fmaxf(acc[i][0] + bb0.x, 0.f);
            r0.y = fmaxf(acc[i][1] + bb0.y, 0.f);
            r0.z = fmaxf(acc[i][2] + bb0.z, 0.f);
            r0.w = fmaxf(acc[i][3] + bb0.w, 0.f);
            r1.x = fmaxf(acc[i][4] + bb1.x, 0.f);
            r1.y = fmaxf(acc[i][5] + bb1.y, 0.f);
            r1.z = fmaxf(acc[i][6] + bb1.z, 0.f);
            r1.w = fmaxf(acc[i][7] + bb1.w, 0.f);
            *reinterpret_cast<float4*>(&out[(size_t)node * F + jg * 4])      = r0;
            *reinterpret_cast<float4*>(&out[(size_t)node * F + 64 + jg * 4]) = r1;
        }
    }
}

// ---------------- final FC: 128 -> 2 -----------------------------------------
__global__ void fc_kernel(const float* __restrict__ h, const float* __restrict__ wfc,
                          const float* __restrict__ bfc, float* __restrict__ out) {
    int gw   = (blockIdx.x * blockDim.x + threadIdx.x) >> 5;
    int lane = threadIdx.x & 31;
    if (gw >= N_NODES) return;
    float4 v  = __ldg(reinterpret_cast<const float4*>(h) + (size_t)gw * 32 + lane);
    float4 w0 = __ldg(reinterpret_cast<const float4*>(wfc) + lane);
    float4 w1 = __ldg(reinterpret_cast<const float4*>(wfc) + 32 + lane);
    float p0 = v.x * w0.x + v.y * w0.y + v.z * w0.z + v.w * w0.w;
    float p1 = v.x * w1.x + v.y * w1.y + v.z * w1.z + v.w * w1.w;
    #pragma unroll
    for (int o = 16; o > 0; o >>= 1) {
        p0 += __shfl_xor_sync(0xffffffffu, p0, o);
        p1 += __shfl_xor_sync(0xffffffffu, p1, o);
    }
    if (lane == 0) {
        out[(size_t)gw * 2 + 0] = p0 + __ldg(&bfc[0]);
        out[(size_t)gw * 2 + 1] = p1 + __ldg(&bfc[1]);
    }
}

// ---------------- launch ------------------------------------------------------
extern "C" void kernel_launch(void* const* d_in, const int* in_sizes, int n_in,
                              void* d_out, int out_size) {
    const float* x   = (const float*)d_in[0];
    const int*   ei  = (const int*)d_in[1];   // int32 words; dtype detected on device
    const float* w1l = (const float*)d_in[2];
    const float* b1  = (const float*)d_in[3];
    const float* w1r = (const float*)d_in[4];
    const float* w2l = (const float*)d_in[5];
    const float* b2  = (const float*)d_in[6];
    const float* w2r = (const float*)d_in[7];
    const float* w3l = (const float*)d_in[8];
    const float* b3  = (const float*)d_in[9];
    const float* w3r = (const float*)d_in[10];
    const float* wfc = (const float*)d_in[11];
    const float* bfc = (const float*)d_in[12];
    float* out = (float*)d_out;

    float *agg, *h0, *h1;
    cudaGetSymbolAddress((void**)&agg, g_agg);
    cudaGetSymbolAddress((void**)&h0,  g_h0);
    cudaGetSymbolAddress((void**)&h1,  g_h1);

    cudaFuncSetAttribute(gemm_kernel, cudaFuncAttributeMaxDynamicSharedMemorySize, GEMM_SMEM);

    const int EB = (N_EDGES + 255) / 256;      // 12500
    const int NB = (N_NODES + 255) / 256;      // 391
    const int WB = (N_NODES * 32 + 255) / 256; // warp-per-node grids: 12500
    const int GB = (N_NODES + BN - 1) / BN;    // 1563

    zero_deg_kernel<<<NB, 256>>>();
    detect_kernel<<<EB, 256>>>(ei);
    edge_prep_kernel<<<EB, 256>>>(ei);
    scan_kernel<<<1, 1024>>>();
    csr_fill_kernel<<<EB, 256>>>();

    // layer 1
    agg_kernel<<<WB, 256>>>(x, agg);
    gemm_kernel<<<GB, 256, GEMM_SMEM>>>(agg, x, w1l, w1r, b1, h0);
    // layer 2
    agg_kernel<<<WB, 256>>>(h0, agg);
    gemm_kernel<<<GB, 256, GEMM_SMEM>>>(agg, h0, w2l, w2r, b2, h1);
    // layer 3
    agg_kernel<<<WB, 256>>>(h1, agg);
    gemm_kernel<<<GB, 256, GEMM_SMEM>>>(agg, h1, w3l, w3r, b3, h0);
    // final fc
    fc_kernel<<<WB, 256>>>(h0, wfc, bfc, out);
}

// round 4
// speedup vs baseline: 3.1642x; 3.1642x over previous
#include <cuda_runtime.h>
#include <cuda_bf16.h>
#include <cstdint>

#define N_NODES 100000
#define N_EDGES 3200000
#define F 128
#define NBLK 98            // ceil(N_NODES/1024)

// ---------------- scratch (static device globals; no allocation) -------------
__device__ int   g_is64;
__device__ int   g_src[N_EDGES];
__device__ int   g_dst[N_EDGES];
__device__ int   g_csr_src[N_EDGES];
__device__ int   g_deg[N_NODES];
__device__ int   g_off[N_NODES + 1];
__device__ int   g_cursor[N_NODES];
__device__ int   g_part[128];
__device__ float g_deginv[N_NODES];
__device__ float g_agg[(size_t)N_NODES * F];
__device__ float g_h0[(size_t)N_NODES * F];
__device__ float g_h1[(size_t)N_NODES * F];

// ---------------- setup kernels ---------------------------------------------
__global__ void zero_deg_kernel() {
    int i = blockIdx.x * blockDim.x + threadIdx.x;
    if (i < N_NODES) g_deg[i] = 0;
    if (i == 0) g_is64 = 1;
}

__global__ void detect_kernel(const int* __restrict__ w) {
    int i = blockIdx.x * blockDim.x + threadIdx.x;
    if (i < N_EDGES) { if (w[2 * i + 1] != 0) g_is64 = 0; }
}

__global__ void edge_prep_kernel(const int* __restrict__ w) {
    int e = blockIdx.x * blockDim.x + threadIdx.x;
    if (e < N_EDGES) {
        int s, d;
        if (g_is64) { s = w[2 * e]; d = w[2 * (N_EDGES + e)]; }
        else        { s = w[e];     d = w[N_EDGES + e]; }
        s = min(max(s, 0), N_NODES - 1);
        d = min(max(d, 0), N_NODES - 1);
        g_src[e] = s; g_dst[e] = d;
        atomicAdd(&g_deg[d], 1);
    }
}

// ---- multi-block exclusive scan: deg -> off, deginv --------------------------
__global__ void scan1_kernel() {
    __shared__ int wsum[32];
    int b = blockIdx.x, t = threadIdx.x, lane = t & 31, w = t >> 5;
    int i = b * 1024 + t;
    int v = (i < N_NODES) ? g_deg[i] : 0;
    int x = v;
    #pragma unroll
    for (int d = 1; d < 32; d <<= 1) {
        int y = __shfl_up_sync(0xffffffffu, x, d);
        if (lane >= d) x += y;
    }
    if (lane == 31) wsum[w] = x;
    __syncthreads();
    if (w == 0) {
        int y = wsum[lane];
        #pragma unroll
        for (int d = 1; d < 32; d <<= 1) {
            int z = __shfl_up_sync(0xffffffffu, y, d);
            if (lane >= d) y += z;
        }
        wsum[lane] = y;
    }
    __syncthreads();
    int excl = (x - v) + (w > 0 ? wsum[w - 1] : 0);
    if (i < N_NODES) {
        g_off[i] = excl;
        g_deginv[i] = 1.0f / fmaxf((float)v, 1.0f);
    }
    if (t == 1023) g_part[b] = excl + v;
}

__global__ void scan2_kernel() {   // 1 block, 128 threads: scan NBLK partials
    __shared__ int wsum[4];
    int t = threadIdx.x, lane = t & 31, w = t >> 5;
    int v = (t < NBLK) ? g_part[t] : 0;
    int x = v;
    #pragma unroll
    for (int d = 1; d < 32; d <<= 1) {
        int y = __shfl_up_sync(0xffffffffu, x, d);
        if (lane >= d) x += y;
    }
    if (lane == 31) wsum[w] = x;
    __syncthreads();
    int base = 0;
    for (int q = 0; q < w; ++q) base += wsum[q];
    int excl = base + (x - v);
    if (t < NBLK) g_part[t] = excl;
    if (t == NBLK - 1) g_off[N_NODES] = excl + v;
}

__global__ void scan3_kernel() {
    int b = blockIdx.x, t = threadIdx.x;
    int i = b * 1024 + t;
    if (i < N_NODES) {
        int o = g_off[i] + g_part[b];
        g_off[i] = o;
        g_cursor[i] = o;
    }
}

__global__ void csr_fill_kernel() {
    int e = blockIdx.x * blockDim.x + threadIdx.x;
    if (e < N_EDGES) {
        int d = g_dst[e];
        int p = atomicAdd(&g_cursor[d], 1);
        if (p >= 0 && p < N_EDGES) g_csr_src[p] = g_src[e];
    }
}

// ---------------- aggregation: warp per node, pull via CSR -------------------
__global__ void agg_kernel(const float* __restrict__ in, float* __restrict__ out) {
    int gw   = (blockIdx.x * blockDim.x + threadIdx.x) >> 5;
    int lane = threadIdx.x & 31;
    if (gw >= N_NODES) return;
    int off0 = g_off[gw];
    int off1 = g_off[gw + 1];
    float4 acc = make_float4(0.f, 0.f, 0.f, 0.f);
    for (int base = off0; base < off1; base += 32) {
        int idx = base + lane;
        int s = (idx < off1) ? g_csr_src[idx] : 0;
        int cnt = min(32, off1 - base);
        #pragma unroll 4
        for (int j = 0; j < cnt; ++j) {
            int sj = __shfl_sync(0xffffffffu, s, j);
            const float4 v = __ldg(reinterpret_cast<const float4*>(in) + (size_t)sj * 32 + lane);
            acc.x += v.x; acc.y += v.y; acc.z += v.z; acc.w += v.w;
        }
    }
    float dinv = g_deginv[gw];
    float4 r = make_float4(acc.x * dinv, acc.y * dinv, acc.z * dinv, acc.w * dinv);
    reinterpret_cast<float4*>(out)[(size_t)gw * 32 + lane] = r;
}

// ---------------- tf32 mma.sync GEMM -----------------------------------------
// C[128n x 128o] = relu( agg@Wl^T + x@Wr^T + b ); fc_mode fuses final 128->2 FC.
// 256 threads = 8 warps in 4(m) x 2(n) grid; warp tile 32x64; frag m16n8k8.
#define AS_STRIDE 132
#define SM_BIAS  0
#define SM_WFC   512
#define SM_FCB   1536
#define SM_A     2560
#define SM_W     (SM_A + 128 * AS_STRIDE * 4)      // 2560 + 67584
#define GEMM_SMEM (SM_W + 128 * AS_STRIDE * 4)     // 137728

__device__ __forceinline__ uint32_t f2tf32(float x) {
    uint32_t y;
    asm("cvt.rna.tf32.f32 %0, %1;" : "=r"(y) : "f"(x));
    return y;
}

__device__ __forceinline__ void mma_tf32(float* c, uint32_t a0, uint32_t a1, uint32_t a2,
                                         uint32_t a3, uint32_t b0, uint32_t b1) {
    asm volatile(
        "mma.sync.aligned.m16n8k8.row.col.f32.tf32.tf32.f32 "
        "{%0,%1,%2,%3}, {%4,%5,%6,%7}, {%8,%9}, {%0,%1,%2,%3};"
        : "+f"(c[0]), "+f"(c[1]), "+f"(c[2]), "+f"(c[3])
        : "r"(a0), "r"(a1), "r"(a2), "r"(a3), "r"(b0), "r"(b1));
}

__global__ void __launch_bounds__(256, 1) gemm_mma_kernel(
    const float* __restrict__ agg, const float* __restrict__ xin,
    const float* __restrict__ wl,  const float* __restrict__ wr,
    const float* __restrict__ bias, float* __restrict__ out,
    const float* __restrict__ wfc, const float* __restrict__ bfc, int fc_mode)
{
    extern __shared__ __align__(16) char smem[];
    float*    biasS = reinterpret_cast<float*>(smem + SM_BIAS);
    float*    wfcS  = reinterpret_cast<float*>(smem + SM_WFC);
    float*    fcbuf = reinterpret_cast<float*>(smem + SM_FCB);
    uint32_t* As    = reinterpret_cast<uint32_t*>(smem + SM_A);
    uint32_t* Ws    = reinterpret_cast<uint32_t*>(smem + SM_W);

    int t = threadIdx.x, wid = t >> 5, lane = t & 31;
    int g = lane >> 2, q = lane & 3;
    int n0 = blockIdx.x * 128;
    const int row_limit = N_NODES - n0;

    if (t < 128) biasS[t] = bias[t];
    if (t < 256) {
        wfcS[t] = fc_mode ? wfc[t] : 0.f;
        fcbuf[t] = 0.f;
    }

    const int m_off = (wid & 3) * 32;
    const int n_off = (wid >> 2) * 64;

    float acc[2][8][4];
    #pragma unroll
    for (int mi = 0; mi < 2; ++mi)
        #pragma unroll
        for (int ni = 0; ni < 8; ++ni)
            #pragma unroll
            for (int c = 0; c < 4; ++c) acc[mi][ni][c] = 0.f;

    #pragma unroll 1
    for (int chunk = 0; chunk < 2; ++chunk) {
        const float* Asrc = chunk ? xin : agg;
        const float* Wsrc = chunk ? wr : wl;
        __syncthreads();   // epilogue of previous chunk done before smem reuse
        #pragma unroll 4
        for (int idx = t; idx < 128 * 32; idx += 256) {
            int r = idx >> 5, c4 = idx & 31;
            float4 v = make_float4(0.f, 0.f, 0.f, 0.f);
            if (r < row_limit)
                v = __ldg(reinterpret_cast<const float4*>(Asrc + (size_t)(n0 + r) * F) + c4);
            uint32_t* p = As + r * AS_STRIDE + c4 * 4;
            p[0] = f2tf32(v.x); p[1] = f2tf32(v.y); p[2] = f2tf32(v.z); p[3] = f2tf32(v.w);
        }
        #pragma unroll 4
        for (int idx = t; idx < 128 * 32; idx += 256) {
            int r = idx >> 5, c4 = idx & 31;
            float4 v = __ldg(reinterpret_cast<const float4*>(Wsrc + (size_t)r * F) + c4);
            uint32_t* p = Ws + r * AS_STRIDE + c4 * 4;
            p[0] = f2tf32(v.x); p[1] = f2tf32(v.y); p[2] = f2tf32(v.z); p[3] = f2tf32(v.w);
        }
        __syncthreads();

        #pragma unroll 4
        for (int k0 = 0; k0 < 128; k0 += 8) {
            uint32_t bf[8][2];
            #pragma unroll
            for (int ni = 0; ni < 8; ++ni) {
                const uint32_t* wp = Ws + (n_off + ni * 8 + g) * AS_STRIDE + k0 + q;
                bf[ni][0] = wp[0];
                bf[ni][1] = wp[4];
            }
            #pragma unroll
            for (int mi = 0; mi < 2; ++mi) {
                const uint32_t* ap = As + (m_off + mi * 16 + g) * AS_STRIDE + k0 + q;
                uint32_t a0 = ap[0];
                uint32_t a1 = ap[8 * AS_STRIDE];
                uint32_t a2 = ap[4];
                uint32_t a3 = ap[8 * AS_STRIDE + 4];
                #pragma unroll
                for (int ni = 0; ni < 8; ++ni)
                    mma_tf32(acc[mi][ni], a0, a1, a2, a3, bf[ni][0], bf[ni][1]);
            }
        }
    }

    // epilogue: bias + relu, then store h (layers 1-2) or fused fc (layer 3)
    float fc0 = 0.f, fc1 = 0.f;
    #pragma unroll
    for (int mi = 0; mi < 2; ++mi) {
        #pragma unroll
        for (int rr = 0; rr < 2; ++rr) {
            int row = m_off + mi * 16 + g + rr * 8;
            int node = n0 + row;
            float rfc0 = 0.f, rfc1 = 0.f;
            #pragma unroll
            for (int ni = 0; ni < 8; ++ni) {
                int col = n_off + ni * 8 + q * 2;
                float h0 = fmaxf(acc[mi][ni][rr * 2 + 0] + biasS[col], 0.f);
                float h1 = fmaxf(acc[mi][ni][rr * 2 + 1] + biasS[col + 1], 0.f);
                if (!fc_mode) {
                    if (node < N_NODES) {
                        float2 v = make_float2(h0, h1);
                        *reinterpret_cast<float2*>(out + (size_t)node * F + col) = v;
                    }
                } else {
                    rfc0 += h0 * wfcS[col] + h1 * wfcS[col + 1];
                    rfc1 += h0 * wfcS[128 + col] + h1 * wfcS[128 + col + 1];
                }
            }
            if (fc_mode) {
                // reduce across the 4 threads of the quad (same row, different cols)
                #pragma unroll
                for (int o = 1; o < 4; o <<= 1) {
                    rfc0 += __shfl_xor_sync(0xffffffffu, rfc0, o);
                    rfc1 += __shfl_xor_sync(0xffffffffu, rfc1, o);
                }
                if (q == 0) {   // combine the two n-half warps via smem atomics
                    atomicAdd(&fcbuf[row * 2 + 0], rfc0);
                    atomicAdd(&fcbuf[row * 2 + 1], rfc1);
                }
            }
            (void)fc0; (void)fc1;
        }
    }
    if (fc_mode) {
        __syncthreads();
        if (t < 256) {
            int row = t >> 1, o = t & 1;
            int node = n0 + row;
            if (node < N_NODES)
                out[(size_t)node * 2 + o] = fcbuf[t] + __ldg(&bfc[o]);
        }
    }
}

// ---------------- launch ------------------------------------------------------
extern "C" void kernel_launch(void* const* d_in, const int* in_sizes, int n_in,
                              void* d_out, int out_size) {
    const float* x   = (const float*)d_in[0];
    const int*   ei  = (const int*)d_in[1];
    const float* w1l = (const float*)d_in[2];
    const float* b1  = (const float*)d_in[3];
    const float* w1r = (const float*)d_in[4];
    const float* w2l = (const float*)d_in[5];
    const float* b2  = (const float*)d_in[6];
    const float* w2r = (const float*)d_in[7];
    const float* w3l = (const float*)d_in[8];
    const float* b3  = (const float*)d_in[9];
    const float* w3r = (const float*)d_in[10];
    const float* wfc = (const float*)d_in[11];
    const float* bfc = (const float*)d_in[12];
    float* out = (float*)d_out;

    float *agg, *h0, *h1;
    cudaGetSymbolAddress((void**)&agg, g_agg);
    cudaGetSymbolAddress((void**)&h0,  g_h0);
    cudaGetSymbolAddress((void**)&h1,  g_h1);

    cudaFuncSetAttribute(gemm_mma_kernel, cudaFuncAttributeMaxDynamicSharedMemorySize, GEMM_SMEM);

    const int EB = (N_EDGES + 255) / 256;
    const int NB = (N_NODES + 255) / 256;
    const int WB = (N_NODES * 32 + 255) / 256;
    const int GB = (N_NODES + 127) / 128;   // 782

    zero_deg_kernel<<<NB, 256>>>();
    detect_kernel<<<EB, 256>>>(ei);
    edge_prep_kernel<<<EB, 256>>>(ei);
    scan1_kernel<<<NBLK, 1024>>>();
    scan2_kernel<<<1, 128>>>();
    scan3_kernel<<<NBLK, 1024>>>();
    csr_fill_kernel<<<EB, 256>>>();

    // layer 1
    agg_kernel<<<WB, 256>>>(x, agg);
    gemm_mma_kernel<<<GB, 256, GEMM_SMEM>>>(agg, x, w1l, w1r, b1, h0, wfc, bfc, 0);
    // layer 2
    agg_kernel<<<WB, 256>>>(h0, agg);
    gemm_mma_kernel<<<GB, 256, GEMM_SMEM>>>(agg, h0, w2l, w2r, b2, h1, wfc, bfc, 0);
    // layer 3 + fused fc
    agg_kernel<<<WB, 256>>>(h1, agg);
    gemm_mma_kernel<<<GB, 256, GEMM_SMEM>>>(agg, h1, w3l, w3r, b3, out, wfc, bfc, 1);
}

// round 7
// speedup vs baseline: 4.6894x; 1.4820x over previous
#include <cuda_runtime.h>
#include <cuda_fp16.h>
#include <cstdint>

#define N_NODES 100000
#define N_EDGES 3200000
#define F 128
#define NBLK 98            // ceil(N_NODES/1024)

// ---- bit casts (no intrinsic exists for half2<->u32) ------------------------
__device__ __forceinline__ uint32_t h2u(__half2 h) {
    return *reinterpret_cast<uint32_t*>(&h);
}
__device__ __forceinline__ __half2 u2h(uint32_t u) {
    return *reinterpret_cast<__half2*>(&u);
}

// ---------------- scratch (static device globals; no allocation) -------------
__device__ int      g_is64;
__device__ int      g_src[N_EDGES];
__device__ int      g_dst[N_EDGES];
__device__ int      g_csr_src[N_EDGES];
__device__ int      g_deg[N_NODES];
__device__ int      g_off[N_NODES + 1];
__device__ int      g_cursor[N_NODES];
__device__ int      g_part[128];
__device__ float    g_deginv[N_NODES];
__device__ __align__(16) uint32_t g_x16[(size_t)N_NODES * 64];    // fp16x2 features
__device__ __align__(16) uint32_t g_agg16[(size_t)N_NODES * 64];
__device__ __align__(16) uint32_t g_ha[(size_t)N_NODES * 64];
__device__ __align__(16) uint32_t g_hb[(size_t)N_NODES * 64];

// ---------------- setup kernels ---------------------------------------------
__global__ void zero_deg_kernel() {
    int i = blockIdx.x * blockDim.x + threadIdx.x;
    if (i < N_NODES) g_deg[i] = 0;
    if (i == 0) g_is64 = 1;
}

__global__ void detect_kernel(const int* __restrict__ w) {
    int i = blockIdx.x * blockDim.x + threadIdx.x;
    if (i < N_EDGES) { if (w[2 * i + 1] != 0) g_is64 = 0; }
}

__global__ void edge_prep_kernel(const int* __restrict__ w) {
    int e = blockIdx.x * blockDim.x + threadIdx.x;
    if (e < N_EDGES) {
        int s, d;
        if (g_is64) { s = w[2 * e]; d = w[2 * (N_EDGES + e)]; }
        else        { s = w[e];     d = w[N_EDGES + e]; }
        s = min(max(s, 0), N_NODES - 1);
        d = min(max(d, 0), N_NODES - 1);
        g_src[e] = s; g_dst[e] = d;
        atomicAdd(&g_deg[d], 1);
    }
}

__global__ void convert_x_kernel(const float* __restrict__ x) {
    size_t i = (size_t)blockIdx.x * blockDim.x + threadIdx.x;
    if (i < (size_t)N_NODES * 64) {
        float2 v = reinterpret_cast<const float2*>(x)[i];
        g_x16[i] = h2u(__float22half2_rn(v));
    }
}

// ---- multi-block exclusive scan: deg -> off, deginv --------------------------
__global__ void scan1_kernel() {
    __shared__ int wsum[32];
    int b = blockIdx.x, t = threadIdx.x, lane = t & 31, w = t >> 5;
    int i = b * 1024 + t;
    int v = (i < N_NODES) ? g_deg[i] : 0;
    int x = v;
    #pragma unroll
    for (int d = 1; d < 32; d <<= 1) {
        int y = __shfl_up_sync(0xffffffffu, x, d);
        if (lane >= d) x += y;
    }
    if (lane == 31) wsum[w] = x;
    __syncthreads();
    if (w == 0) {
        int y = wsum[lane];
        #pragma unroll
        for (int d = 1; d < 32; d <<= 1) {
            int z = __shfl_up_sync(0xffffffffu, y, d);
            if (lane >= d) y += z;
        }
        wsum[lane] = y;
    }
    __syncthreads();
    int excl = (x - v) + (w > 0 ? wsum[w - 1] : 0);
    if (i < N_NODES) {
        g_off[i] = excl;
        g_deginv[i] = 1.0f / fmaxf((float)v, 1.0f);
    }
    if (t == 1023) g_part[b] = excl + v;
}

__global__ void scan2_kernel() {
    __shared__ int wsum[4];
    int t = threadIdx.x, lane = t & 31, w = t >> 5;
    int v = (t < NBLK) ? g_part[t] : 0;
    int x = v;
    #pragma unroll
    for (int d = 1; d < 32; d <<= 1) {
        int y = __shfl_up_sync(0xffffffffu, x, d);
        if (lane >= d) x += y;
    }
    if (lane == 31) wsum[w] = x;
    __syncthreads();
    int base = 0;
    for (int q = 0; q < w; ++q) base += wsum[q];
    int excl = base + (x - v);
    if (t < NBLK) g_part[t] = excl;
    if (t == NBLK - 1) g_off[N_NODES] = excl + v;
}

__global__ void scan3_kernel() {
    int b = blockIdx.x, t = threadIdx.x;
    int i = b * 1024 + t;
    if (i < N_NODES) {
        int o = g_off[i] + g_part[b];
        g_off[i] = o;
        g_cursor[i] = o;
    }
}

__global__ void csr_fill_kernel() {
    int e = blockIdx.x * blockDim.x + threadIdx.x;
    if (e < N_EDGES) {
        int d = g_dst[e];
        int p = atomicAdd(&g_cursor[d], 1);
        if (p >= 0 && p < N_EDGES) g_csr_src[p] = g_src[e];
    }
}

// ---------------- aggregation: warp per node, fp16 gather ---------------------
__global__ void agg_kernel(const uint32_t* __restrict__ in, uint32_t* __restrict__ out) {
    int gw   = (blockIdx.x * blockDim.x + threadIdx.x) >> 5;
    int lane = threadIdx.x & 31;
    if (gw >= N_NODES) return;
    int off0 = g_off[gw];
    int off1 = g_off[gw + 1];
    float4 acc = make_float4(0.f, 0.f, 0.f, 0.f);
    const uint2* inv = reinterpret_cast<const uint2*>(in);
    for (int base = off0; base < off1; base += 32) {
        int idx = base + lane;
        int s = (idx < off1) ? g_csr_src[idx] : 0;
        int cnt = min(32, off1 - base);
        #pragma unroll 8
        for (int j = 0; j < cnt; ++j) {
            int sj = __shfl_sync(0xffffffffu, s, j);
            uint2 v = __ldg(inv + (size_t)sj * 32 + lane);   // 4 fp16
            float2 f0 = __half22float2(u2h(v.x));
            float2 f1 = __half22float2(u2h(v.y));
            acc.x += f0.x; acc.y += f0.y; acc.z += f1.x; acc.w += f1.y;
        }
    }
    float dinv = g_deginv[gw];
    uint2 r;
    r.x = h2u(__floats2half2_rn(acc.x * dinv, acc.y * dinv));
    r.y = h2u(__floats2half2_rn(acc.z * dinv, acc.w * dinv));
    reinterpret_cast<uint2*>(out)[(size_t)gw * 32 + lane] = r;
}

// ---------------- fp16 mma.sync GEMM -----------------------------------------
// C[128n x 128o] = relu( agg@Wl^T + h@Wr^T + b ); fc_mode fuses final 128->2 FC.
// 256 threads = 8 warps in 4(m) x 2(n); warp tile 32x64; frag m16n8k16.
// smem tiles: [128 rows][68 uint32] (64 used = 128 fp16; pad 4 -> conflict-free frags)
#define TS 68
#define SM_BIAS  0
#define SM_WFC   512
#define SM_FCB   1536
#define SM_A     2560
#define SM_W     (SM_A + 128 * TS * 4)          // 2560 + 34816
#define GEMM_SMEM (SM_W + 128 * TS * 4)         // 72192

__device__ __forceinline__ void mma_f16(float* c, uint32_t a0, uint32_t a1, uint32_t a2,
                                        uint32_t a3, uint32_t b0, uint32_t b1) {
    asm volatile(
        "mma.sync.aligned.m16n8k16.row.col.f32.f16.f16.f32 "
        "{%0,%1,%2,%3}, {%4,%5,%6,%7}, {%8,%9}, {%0,%1,%2,%3};"
        : "+f"(c[0]), "+f"(c[1]), "+f"(c[2]), "+f"(c[3])
        : "r"(a0), "r"(a1), "r"(a2), "r"(a3), "r"(b0), "r"(b1));
}

__global__ void __launch_bounds__(256) gemm_mma_kernel(
    const uint32_t* __restrict__ aggi, const uint32_t* __restrict__ xini,
    const float* __restrict__ wl,  const float* __restrict__ wr,
    const float* __restrict__ bias, uint32_t* __restrict__ outh,
    float* __restrict__ outf,
    const float* __restrict__ wfc, const float* __restrict__ bfc, int fc_mode)
{
    extern __shared__ __align__(16) char smem[];
    float*    biasS = reinterpret_cast<float*>(smem + SM_BIAS);
    float*    wfcS  = reinterpret_cast<float*>(smem + SM_WFC);
    float*    fcbuf = reinterpret_cast<float*>(smem + SM_FCB);
    uint32_t* As    = reinterpret_cast<uint32_t*>(smem + SM_A);
    uint32_t* Ws    = reinterpret_cast<uint32_t*>(smem + SM_W);

    int t = threadIdx.x, wid = t >> 5, lane = t & 31;
    int g = lane >> 2, q = lane & 3;
    int n0 = blockIdx.x * 128;
    const int row_limit = N_NODES - n0;

    if (t < 128) biasS[t] = bias[t];
    if (t < 256) {
        wfcS[t] = fc_mode ? wfc[t] : 0.f;
        fcbuf[t] = 0.f;
    }

    const int m_off = (wid & 3) * 32;
    const int n_off = (wid >> 2) * 64;

    float acc[2][8][4];
    #pragma unroll
    for (int mi = 0; mi < 2; ++mi)
        #pragma unroll
        for (int ni = 0; ni < 8; ++ni)
            #pragma unroll
            for (int c = 0; c < 4; ++c) acc[mi][ni][c] = 0.f;

    #pragma unroll 1
    for (int chunk = 0; chunk < 2; ++chunk) {
        const uint32_t* Asrc = chunk ? xini : aggi;
        const float*    Wsrc = chunk ? wr : wl;
        __syncthreads();
        // A tile: fp16 source; each row = 64 uint32 = 16 uint4
        #pragma unroll
        for (int idx = t; idx < 128 * 16; idx += 256) {
            int r = idx >> 4, c16 = idx & 15;
            uint4 v = make_uint4(0u, 0u, 0u, 0u);
            if (r < row_limit)
                v = __ldg(reinterpret_cast<const uint4*>(Asrc + (size_t)(n0 + r) * 64) + c16);
            *reinterpret_cast<uint4*>(As + r * TS + c16 * 4) = v;
        }
        // W tile: fp32 source -> fp16x2
        #pragma unroll
        for (int idx = t; idx < 128 * 32; idx += 256) {
            int r = idx >> 5, c4 = idx & 31;
            float4 v = __ldg(reinterpret_cast<const float4*>(Wsrc + (size_t)r * F) + c4);
            uint32_t* p = Ws + r * TS + c4 * 2;
            p[0] = h2u(__floats2half2_rn(v.x, v.y));
            p[1] = h2u(__floats2half2_rn(v.z, v.w));
        }
        __syncthreads();

        #pragma unroll
        for (int k0 = 0; k0 < 64; k0 += 8) {      // k-pairs: 8 per m16n8k16 step
            uint32_t bf[8][2];
            #pragma unroll
            for (int ni = 0; ni < 8; ++ni) {
                const uint32_t* wp = Ws + (n_off + ni * 8 + g) * TS + k0 + q;
                bf[ni][0] = wp[0];
                bf[ni][1] = wp[4];
            }
            #pragma unroll
            for (int mi = 0; mi < 2; ++mi) {
                const uint32_t* ap = As + (m_off + mi * 16 + g) * TS + k0 + q;
                uint32_t a0 = ap[0];
                uint32_t a1 = ap[8 * TS];
                uint32_t a2 = ap[4];
                uint32_t a3 = ap[8 * TS + 4];
                #pragma unroll
                for (int ni = 0; ni < 8; ++ni)
                    mma_f16(acc[mi][ni], a0, a1, a2, a3, bf[ni][0], bf[ni][1]);
            }
        }
    }

    // epilogue: bias + relu -> fp16 h store, or fused fc
    #pragma unroll
    for (int mi = 0; mi < 2; ++mi) {
        #pragma unroll
        for (int rr = 0; rr < 2; ++rr) {
            int row = m_off + mi * 16 + g + rr * 8;
            int node = n0 + row;
            float rfc0 = 0.f, rfc1 = 0.f;
            #pragma unroll
            for (int ni = 0; ni < 8; ++ni) {
                int col = n_off + ni * 8 + q * 2;
                float h0 = fmaxf(acc[mi][ni][rr * 2 + 0] + biasS[col], 0.f);
                float h1 = fmaxf(acc[mi][ni][rr * 2 + 1] + biasS[col + 1], 0.f);
                if (!fc_mode) {
                    if (node < N_NODES)
                        outh[(size_t)node * 64 + (col >> 1)] =
                            h2u(__floats2half2_rn(h0, h1));
                } else {
                    rfc0 += h0 * wfcS[col] + h1 * wfcS[col + 1];
                    rfc1 += h0 * wfcS[128 + col] + h1 * wfcS[128 + col + 1];
                }
            }
            if (fc_mode) {
                #pragma unroll
                for (int o = 1; o < 4; o <<= 1) {
                    rfc0 += __shfl_xor_sync(0xffffffffu, rfc0, o);
                    rfc1 += __shfl_xor_sync(0xffffffffu, rfc1, o);
                }
                if (q == 0) {
                    atomicAdd(&fcbuf[row * 2 + 0], rfc0);
                    atomicAdd(&fcbuf[row * 2 + 1], rfc1);
                }
            }
        }
    }
    if (fc_mode) {
        __syncthreads();
        if (t < 256) {
            int row = t >> 1, o = t & 1;
            int node = n0 + row;
            if (node < N_NODES)
                outf[(size_t)node * 2 + o] = fcbuf[t] + __ldg(&bfc[o]);
        }
    }
}

// ---------------- launch ------------------------------------------------------
extern "C" void kernel_launch(void* const* d_in, const int* in_sizes, int n_in,
                              void* d_out, int out_size) {
    const float* x   = (const float*)d_in[0];
    const int*   ei  = (const int*)d_in[1];
    const float* w1l = (const float*)d_in[2];
    const float* b1  = (const float*)d_in[3];
    const float* w1r = (const float*)d_in[4];
    const float* w2l = (const float*)d_in[5];
    const float* b2  = (const float*)d_in[6];
    const float* w2r = (const float*)d_in[7];
    const float* w3l = (const float*)d_in[8];
    const float* b3  = (const float*)d_in[9];
    const float* w3r = (const float*)d_in[10];
    const float* wfc = (const float*)d_in[11];
    const float* bfc = (const float*)d_in[12];
    float* out = (float*)d_out;

    uint32_t *x16, *agg16, *ha, *hb;
    cudaGetSymbolAddress((void**)&x16,   g_x16);
    cudaGetSymbolAddress((void**)&agg16, g_agg16);
    cudaGetSymbolAddress((void**)&ha,    g_ha);
    cudaGetSymbolAddress((void**)&hb,    g_hb);

    cudaFuncSetAttribute(gemm_mma_kernel, cudaFuncAttributeMaxDynamicSharedMemorySize, GEMM_SMEM);

    const int EB = (N_EDGES + 255) / 256;
    const int NB = (N_NODES + 255) / 256;
    const int WB = (N_NODES * 32 + 255) / 256;
    const int GB = (N_NODES + 127) / 128;
    const int CB = (N_NODES * 64 + 255) / 256;

    zero_deg_kernel<<<NB, 256>>>();
    detect_kernel<<<EB, 256>>>(ei);
    edge_prep_kernel<<<EB, 256>>>(ei);
    scan1_kernel<<<NBLK, 1024>>>();
    scan2_kernel<<<1, 128>>>();
    scan3_kernel<<<NBLK, 1024>>>();
    csr_fill_kernel<<<EB, 256>>>();
    convert_x_kernel<<<CB, 256>>>(x);

    // layer 1
    agg_kernel<<<WB, 256>>>(x16, agg16);
    gemm_mma_kernel<<<GB, 256, GEMM_SMEM>>>(agg16, x16, w1l, w1r, b1, ha, out, wfc, bfc, 0);
    // layer 2
    agg_kernel<<<WB, 256>>>(ha, agg16);
    gemm_mma_kernel<<<GB, 256, GEMM_SMEM>>>(agg16, ha, w2l, w2r, b2, hb, out, wfc, bfc, 0);
    // layer 3 + fused fc
    agg_kernel<<<WB, 256>>>(hb, agg16);
    gemm_mma_kernel<<<GB, 256, GEMM_SMEM>>>(agg16, hb, w3l, w3r, b3, ha, out, wfc, bfc, 1);
}